// round 14
// baseline (speedup 1.0000x reference)
#include <cuda_runtime.h>
#include <cstdint>
#include <cstddef>

namespace {
constexpr int kB = 16, kS = 2048, kD = 128, TQ = 64, TK = 64, NT = 512;
constexpr int NKT = kS / TK;   // 32
constexpr int QP = 132;        // Q pitch (floats)
constexpr int KP = 132;        // K pitch
constexpr int VTP = 68;        // V^T pitch ([d=128][tok=64])
constexpr int PP = 68;         // P pitch

struct Smem {
  float Qs[TQ * QP];
  float Ks[TK * KP];
  float VT[kD * VTP];
  float Ps[TQ * PP];
  float Zs[TQ];
  float rZs[TQ];
  float Zp[4][TQ];
  float Vps[4][kD];
  float Vcsum[kD];
};
constexpr int SMEM_BYTES = (int)sizeof(Smem);

constexpr float kC = 0.12752991043f;   // 1/sqrt(128) * log2(e)

__device__ __forceinline__ float exp_mufu(float s) {
  float y = s * kC, r;
  asm("ex2.approx.ftz.f32 %0, %1;" : "=f"(r) : "f"(y));
  return r;
}
__device__ __forceinline__ float exp_poly(float s) {
  float y = s * kC;
  float r = y + 12582912.0f;
  float f = y - (r - 12582912.0f);
  int n = __float_as_int(r);
  float p = 0.0096181f;
  p = fmaf(p, f, 0.0555042f);
  p = fmaf(p, f, 0.2402265f);
  p = fmaf(p, f, 0.6931472f);
  p = fmaf(p, f, 1.0f);
  return __int_as_float(__float_as_int(p) + (n << 23));
}

__device__ __forceinline__ uint32_t f2tf32(float f) {
  uint32_t u; asm("cvt.rna.tf32.f32 %0, %1;" : "=r"(u) : "f"(f)); return u;
}
__device__ __forceinline__ float tff(float f) { return __uint_as_float(f2tf32(f)); }

__device__ __forceinline__ void ldm_x4(uint32_t* r, uint32_t a) {
  asm volatile("ldmatrix.sync.aligned.m8n8.x4.shared.b16 {%0,%1,%2,%3}, [%4];"
               : "=r"(r[0]), "=r"(r[1]), "=r"(r[2]), "=r"(r[3]) : "r"(a));
}
__device__ __forceinline__ void mma_tf32(float c[4], const uint32_t a[4],
                                         uint32_t b0, uint32_t b1) {
  asm volatile(
      "mma.sync.aligned.m16n8k8.row.col.f32.tf32.tf32.f32 "
      "{%0,%1,%2,%3}, {%4,%5,%6,%7}, {%8,%9}, {%0,%1,%2,%3};\n"
      : "+f"(c[0]), "+f"(c[1]), "+f"(c[2]), "+f"(c[3])
      : "r"(a[0]), "r"(a[1]), "r"(a[2]), "r"(a[3]), "r"(b0), "r"(b1));
}
}  // namespace

extern "C" __global__ void __launch_bounds__(NT, 1)
sdpa_kernel(const float* __restrict__ Q, const float* __restrict__ K,
            const float* __restrict__ V, float* __restrict__ out,
            float* __restrict__ attn)
{
  extern __shared__ char smem_raw[];
  Smem& sm = *reinterpret_cast<Smem*>(smem_raw);

  const int qt  = blockIdx.x;
  const int b   = blockIdx.y;
  const int tid = threadIdx.x;
  const int q0  = qt * TQ;
  const int wid  = tid >> 5;
  const int lane = tid & 31;
  const int wr   = wid >> 2;
  const int wc   = wid & 3;
  const int gid  = lane >> 2;
  const int tig  = lane & 3;
  const int r0 = 16 * wr + gid, r1 = r0 + 8;

  const float* Qb = Q + (size_t)b * kS * kD;
  const float* Kb = K + (size_t)b * kS * kD;
  const float* Vb = V + (size_t)b * kS * kD;
  float* outb  = out  + (size_t)b * kS * kD;
  float* attnb = attn + (size_t)b * kS * kS;

  const uint32_t smQ  = (uint32_t)__cvta_generic_to_shared(sm.Qs);
  const uint32_t smK  = (uint32_t)__cvta_generic_to_shared(sm.Ks);
  const uint32_t smVT = (uint32_t)__cvta_generic_to_shared(sm.VT);
  const uint32_t smP  = (uint32_t)__cvta_generic_to_shared(sm.Ps);

  const uint32_t qa_base = smQ + (uint32_t)((16 * wr + (lane & 15)) * QP * 4 + (lane >> 4) * 16);
  const uint32_t pa_base = smP + (uint32_t)((16 * wr + (lane & 15)) * PP * 4 + (lane >> 4) * 16);
  const uint32_t kb_base = smK + (uint32_t)((16 * wc + (lane & 7) + 8 * (lane >> 4)) * KP * 4 +
                                            ((lane >> 3) & 1) * 16);
  const uint32_t vb_base = smVT + (uint32_t)((32 * wc + (lane & 7) + 8 * (lane >> 4)) * VTP * 4 +
                                             ((lane >> 3) & 1) * 16);

  // ---- stage Q (tf32, once) ----
  {
    const float4* Qg = reinterpret_cast<const float4*>(Qb + (size_t)q0 * kD);
#pragma unroll
    for (int j = 0; j < 4; ++j) {
      const int f = tid + j * NT;
      const int r = f >> 5;
      float4 v = Qg[f];
      float4 t = make_float4(tff(v.x), tff(v.y), tff(v.z), tff(v.w));
      *reinterpret_cast<float4*>(&sm.Qs[r * QP + lane * 4]) = t;
    }
  }
  if (tid < TQ) sm.Zs[tid] = (float)q0;

  // ---- prefetch first K/V tile ----
  float4 kreg[4];
  float vreg[16];
  const int vd = 32 * (wid & 3) + lane;
  const int vt0 = 4 * (wid >> 2);
  {
    const float4* Kg = reinterpret_cast<const float4*>(Kb + (size_t)qt * TK * kD);
#pragma unroll
    for (int j = 0; j < 4; ++j) kreg[j] = Kg[tid + j * NT];
    const float* Vg = Vb + (size_t)qt * TK * kD;
#pragma unroll
    for (int j = 0; j < 4; ++j)
#pragma unroll
      for (int t = 0; t < 4; ++t)
        vreg[4 * j + t] = Vg[(size_t)(vt0 + 16 * j + t) * kD + vd];
  }

  float oacc[4][4];
#pragma unroll
  for (int j = 0; j < 4; ++j)
#pragma unroll
    for (int v = 0; v < 4; ++v) oacc[j][v] = 0.f;

  // ================= Phase 1 =================
  for (int kt = qt; kt < NKT; ++kt) {
    const int k0 = kt * TK;
    __syncthreads();

    // stage K (tf32)
#pragma unroll
    for (int j = 0; j < 4; ++j) {
      const int f = tid + j * NT;
      const int r = f >> 5;
      float4 t = make_float4(tff(kreg[j].x), tff(kreg[j].y),
                             tff(kreg[j].z), tff(kreg[j].w));
      *reinterpret_cast<float4*>(&sm.Ks[r * KP + lane * 4]) = t;
    }
    // stage V transposed (tf32)
#pragma unroll
    for (int j = 0; j < 4; ++j) {
      float4 t = make_float4(tff(vreg[4 * j + 0]), tff(vreg[4 * j + 1]),
                             tff(vreg[4 * j + 2]), tff(vreg[4 * j + 3]));
      *reinterpret_cast<float4*>(&sm.VT[vd * VTP + vt0 + 16 * j]) = t;
    }
    // prefetch next tile
    if (kt + 1 < NKT) {
      const float4* Kg = reinterpret_cast<const float4*>(Kb + (size_t)(k0 + TK) * kD);
#pragma unroll
      for (int j = 0; j < 4; ++j) kreg[j] = Kg[tid + j * NT];
      const float* Vg = Vb + (size_t)(k0 + TK) * kD;
#pragma unroll
      for (int j = 0; j < 4; ++j)
#pragma unroll
        for (int t = 0; t < 4; ++t)
          vreg[4 * j + t] = Vg[(size_t)(vt0 + 16 * j + t) * kD + vd];
    }
    __syncthreads();

    // ---- QK^T (register double-buffered fragments) ----
    float sacc[2][4];
#pragma unroll
    for (int j = 0; j < 2; ++j)
#pragma unroll
      for (int v = 0; v < 4; ++v) sacc[j][v] = 0.f;
    {
      uint32_t aq[2][4], bk[2][4];
      ldm_x4(aq[0], qa_base);
      ldm_x4(bk[0], kb_base);
#pragma unroll
      for (int s = 0; s < 16; ++s) {
        const int cur = s & 1, nx = cur ^ 1;
        if (s < 15) {
          ldm_x4(aq[nx], qa_base + (uint32_t)((s + 1) * 32));
          ldm_x4(bk[nx], kb_base + (uint32_t)((s + 1) * 32));
        }
        mma_tf32(sacc[0], aq[cur], bk[cur][0], bk[cur][1]);
        mma_tf32(sacc[1], aq[cur], bk[cur][2], bk[cur][3]);
      }
    }

    // ---- mask + exp (hybrid); attn store; Ps store; Z partials ----
    const bool diag = (kt == qt);
    float rs0 = 0.f, rs1 = 0.f;
    float* arow0 = attnb + (size_t)(q0 + r0) * kS + k0;
    float* arow1 = attnb + (size_t)(q0 + r1) * kS + k0;
#pragma unroll
    for (int j = 0; j < 2; ++j) {
      const int c = 16 * wc + 8 * j + 2 * tig;
      float x00 = exp_mufu(sacc[j][0]);
      float x01 = exp_mufu(sacc[j][1]);
      float x10 = (j == 1) ? exp_poly(sacc[j][2]) : exp_mufu(sacc[j][2]);
      float x11 = (j == 1) ? exp_poly(sacc[j][3]) : exp_mufu(sacc[j][3]);
      float e00, e01, e10, e11;
      if (diag) {
        e00 = (c     > r0) ? x00 : 1.0f;
        e01 = (c + 1 > r0) ? x01 : 1.0f;
        e10 = (c     > r1) ? x10 : 1.0f;
        e11 = (c + 1 > r1) ? x11 : 1.0f;
      } else {
        e00 = x00; e01 = x01; e10 = x10; e11 = x11;
      }
      rs0 += e00 + e01;
      rs1 += e10 + e11;
      *reinterpret_cast<float2*>(arow0 + c) = make_float2(e00, e01);
      *reinterpret_cast<float2*>(arow1 + c) = make_float2(e10, e11);
      *reinterpret_cast<float2*>(&sm.Ps[r0 * PP + c]) = make_float2(tff(e00), tff(e01));
      *reinterpret_cast<float2*>(&sm.Ps[r1 * PP + c]) = make_float2(tff(e10), tff(e11));
    }
    rs0 += __shfl_xor_sync(0xffffffffu, rs0, 1, 4);
    rs0 += __shfl_xor_sync(0xffffffffu, rs0, 2, 4);
    rs1 += __shfl_xor_sync(0xffffffffu, rs1, 1, 4);
    rs1 += __shfl_xor_sync(0xffffffffu, rs1, 2, 4);
    if (tig == 0) { sm.Zp[wc][r0] = rs0; sm.Zp[wc][r1] = rs1; }
    __syncthreads();
    if (tid < TQ)
      sm.Zs[tid] += (sm.Zp[0][tid] + sm.Zp[1][tid]) +
                    (sm.Zp[2][tid] + sm.Zp[3][tid]);

    // ---- PV (register double-buffered fragments) ----
    {
      uint32_t ap[2][4], bv0[2][4], bv1[2][4];
      ldm_x4(ap[0], pa_base);
      ldm_x4(bv0[0], vb_base);
      ldm_x4(bv1[0], vb_base + (uint32_t)(16 * VTP * 4));
#pragma unroll
      for (int kk = 0; kk < 8; ++kk) {
        const int cur = kk & 1, nx = cur ^ 1;
        if (kk < 7) {
          ldm_x4(ap[nx], pa_base + (uint32_t)((kk + 1) * 32));
          ldm_x4(bv0[nx], vb_base + (uint32_t)((kk + 1) * 32));
          ldm_x4(bv1[nx], vb_base + (uint32_t)(16 * VTP * 4 + (kk + 1) * 32));
        }
        mma_tf32(oacc[0], ap[cur], bv0[cur][0], bv0[cur][1]);
        mma_tf32(oacc[1], ap[cur], bv0[cur][2], bv0[cur][3]);
        mma_tf32(oacc[2], ap[cur], bv1[cur][0], bv1[cur][1]);
        mma_tf32(oacc[3], ap[cur], bv1[cur][2], bv1[cur][3]);
      }
    }
  }

  // ================= Phase 2 =================
  __syncthreads();
  if (tid < TQ) sm.rZs[tid] = 1.0f / sm.Zs[tid];
  __syncthreads();

  // lower-region V column sums
  {
    const int vc = tid & 127, vq = tid >> 7;
    float a0 = 0.f, a1 = 0.f, a2 = 0.f, a3 = 0.f;
    for (int t = vq; t < q0; t += 16) {
      a0 += Vb[(size_t)t * kD + vc];
      a1 += Vb[(size_t)(t + 4) * kD + vc];
      a2 += Vb[(size_t)(t + 8) * kD + vc];
      a3 += Vb[(size_t)(t + 12) * kD + vc];
    }
    sm.Vps[vq][vc] = (a0 + a1) + (a2 + a3);
  }

  // lower attn fill = 1/Z
  const int ftr = tid >> 4, ftc = tid & 15;
  for (int kt = 0; kt < qt; ++kt) {
    const int k0 = kt * TK;
#pragma unroll
    for (int p = 0; p < 2; ++p) {
      const int r = ftr + 32 * p;
      const float rz = sm.rZs[r];
      *reinterpret_cast<float4*>(&attnb[(size_t)(q0 + r) * kS + k0 + 4 * ftc]) =
          make_float4(rz, rz, rz, rz);
    }
  }
  __syncthreads();
  if (tid < kD)
    sm.Vcsum[tid] = (sm.Vps[0][tid] + sm.Vps[1][tid]) +
                    (sm.Vps[2][tid] + sm.Vps[3][tid]);
  __syncthreads();

  // rescale upper attn tiles (2 k-tiles in flight)
  {
    const float rzA = sm.rZs[ftr];
    const float rzB = sm.rZs[ftr + 32];
    int kt = qt;
    for (; kt + 1 < NKT; kt += 2) {
      float4* p00 = reinterpret_cast<float4*>(&attnb[(size_t)(q0 + ftr) * kS + kt * TK + 4 * ftc]);
      float4* p01 = reinterpret_cast<float4*>(&attnb[(size_t)(q0 + ftr + 32) * kS + kt * TK + 4 * ftc]);
      float4* p10 = reinterpret_cast<float4*>(&attnb[(size_t)(q0 + ftr) * kS + (kt + 1) * TK + 4 * ftc]);
      float4* p11 = reinterpret_cast<float4*>(&attnb[(size_t)(q0 + ftr + 32) * kS + (kt + 1) * TK + 4 * ftc]);
      float4 v00 = *p00, v01 = *p01, v10 = *p10, v11 = *p11;
      v00.x *= rzA; v00.y *= rzA; v00.z *= rzA; v00.w *= rzA;
      v01.x *= rzB; v01.y *= rzB; v01.z *= rzB; v01.w *= rzB;
      v10.x *= rzA; v10.y *= rzA; v10.z *= rzA; v10.w *= rzA;
      v11.x *= rzB; v11.y *= rzB; v11.z *= rzB; v11.w *= rzB;
      *p00 = v00; *p01 = v01; *p10 = v10; *p11 = v11;
    }
    if (kt < NKT) {
      float4* p00 = reinterpret_cast<float4*>(&attnb[(size_t)(q0 + ftr) * kS + kt * TK + 4 * ftc]);
      float4* p01 = reinterpret_cast<float4*>(&attnb[(size_t)(q0 + ftr + 32) * kS + kt * TK + 4 * ftc]);
      float4 v00 = *p00, v01 = *p01;
      v00.x *= rzA; v00.y *= rzA; v00.z *= rzA; v00.w *= rzA;
      v01.x *= rzB; v01.y *= rzB; v01.z *= rzB; v01.w *= rzB;
      *p00 = v00; *p01 = v01;
    }
  }

  // final output
  {
    const float rz0 = sm.rZs[r0], rz1 = sm.rZs[r1];
#pragma unroll
    for (int j = 0; j < 4; ++j) {
      const int c = 32 * wc + 8 * j + 2 * tig;
      const float vs0 = sm.Vcsum[c], vs1 = sm.Vcsum[c + 1];
      float2 o0 = make_float2(rz0 * (oacc[j][0] + vs0), rz0 * (oacc[j][1] + vs1));
      float2 o1 = make_float2(rz1 * (oacc[j][2] + vs0), rz1 * (oacc[j][3] + vs1));
      *reinterpret_cast<float2*>(&outb[(size_t)(q0 + r0) * kD + c]) = o0;
      *reinterpret_cast<float2*>(&outb[(size_t)(q0 + r1) * kD + c]) = o1;
    }
  }
}

extern "C" void kernel_launch(void* const* d_in, const int* in_sizes, int n_in,
                              void* d_out, int out_size) {
  (void)in_sizes; (void)n_in; (void)out_size;
  const float* Q = (const float*)d_in[0];
  const float* K = (const float*)d_in[1];
  const float* V = (const float*)d_in[2];
  float* out  = (float*)d_out;
  float* attn = out + (size_t)kB * kS * kD;

  cudaFuncSetAttribute(sdpa_kernel, cudaFuncAttributeMaxDynamicSharedMemorySize,
                       SMEM_BYTES);
  dim3 grid(NKT, kB);
  sdpa_kernel<<<grid, NT, SMEM_BYTES>>>(Q, K, V, out, attn);
}

// round 15
// speedup vs baseline: 1.0020x; 1.0020x over previous
#include <cuda_runtime.h>
#include <cstdint>
#include <cstddef>

namespace {
constexpr int kB = 16, kS = 2048, kD = 128, TQ = 64, TK = 64, NT = 512;
constexpr int NKT = kS / TK;   // 32
constexpr int QP = 132;        // Q pitch (floats)
constexpr int KP = 132;        // K pitch
constexpr int VTP = 76;        // V^T pitch: 304B lane stride = 3 mod 8 groups -> conflict-free
constexpr int PP = 68;         // P pitch

struct Smem {
  float Qs[TQ * QP];
  float Ks[TK * KP];
  float VT[kD * VTP];
  float Ps[TQ * PP];
  float Zs[TQ];
  float rZs[TQ];
  float Zp[4][TQ];
  float Vps[4][kD];
  float Vcsum[kD];
};
constexpr int SMEM_BYTES = (int)sizeof(Smem);

constexpr float kC = 0.12752991043f;   // 1/sqrt(128) * log2(e)

__device__ __forceinline__ float exp_mufu(float s) {
  float y = s * kC, r;
  asm("ex2.approx.ftz.f32 %0, %1;" : "=f"(r) : "f"(y));
  return r;
}
__device__ __forceinline__ float exp_poly(float s) {
  float y = s * kC;
  float r = y + 12582912.0f;
  float f = y - (r - 12582912.0f);
  int n = __float_as_int(r);
  float p = 0.0096181f;
  p = fmaf(p, f, 0.0555042f);
  p = fmaf(p, f, 0.2402265f);
  p = fmaf(p, f, 0.6931472f);
  p = fmaf(p, f, 1.0f);
  return __int_as_float(__float_as_int(p) + (n << 23));
}

__device__ __forceinline__ uint32_t f2tf32(float f) {
  uint32_t u; asm("cvt.rna.tf32.f32 %0, %1;" : "=r"(u) : "f"(f)); return u;
}
__device__ __forceinline__ float tff(float f) { return __uint_as_float(f2tf32(f)); }

__device__ __forceinline__ void ldm_x4(uint32_t& r0, uint32_t& r1,
                                       uint32_t& r2, uint32_t& r3, uint32_t a) {
  asm volatile("ldmatrix.sync.aligned.m8n8.x4.shared.b16 {%0,%1,%2,%3}, [%4];"
               : "=r"(r0), "=r"(r1), "=r"(r2), "=r"(r3) : "r"(a));
}
__device__ __forceinline__ void mma_tf32(float c[4], uint32_t a0, uint32_t a1,
                                         uint32_t a2, uint32_t a3,
                                         uint32_t b0, uint32_t b1) {
  asm volatile(
      "mma.sync.aligned.m16n8k8.row.col.f32.tf32.tf32.f32 "
      "{%0,%1,%2,%3}, {%4,%5,%6,%7}, {%8,%9}, {%0,%1,%2,%3};\n"
      : "+f"(c[0]), "+f"(c[1]), "+f"(c[2]), "+f"(c[3])
      : "r"(a0), "r"(a1), "r"(a2), "r"(a3), "r"(b0), "r"(b1));
}
}  // namespace

extern "C" __global__ void __launch_bounds__(NT, 1)
sdpa_kernel(const float* __restrict__ Q, const float* __restrict__ K,
            const float* __restrict__ V, float* __restrict__ out,
            float* __restrict__ attn)
{
  extern __shared__ char smem_raw[];
  Smem& sm = *reinterpret_cast<Smem*>(smem_raw);

  const int qt  = blockIdx.x;
  const int b   = blockIdx.y;
  const int tid = threadIdx.x;
  const int q0  = qt * TQ;
  const int wid  = tid >> 5;
  const int lane = tid & 31;
  const int wr   = wid >> 2;
  const int wc   = wid & 3;
  const int gid  = lane >> 2;
  const int tig  = lane & 3;
  const int r0 = 16 * wr + gid, r1 = r0 + 8;

  const float* Qb = Q + (size_t)b * kS * kD;
  const float* Kb = K + (size_t)b * kS * kD;
  const float* Vb = V + (size_t)b * kS * kD;
  float* outb  = out  + (size_t)b * kS * kD;
  float* attnb = attn + (size_t)b * kS * kS;

  const uint32_t smQ  = (uint32_t)__cvta_generic_to_shared(sm.Qs);
  const uint32_t smK  = (uint32_t)__cvta_generic_to_shared(sm.Ks);
  const uint32_t smVT = (uint32_t)__cvta_generic_to_shared(sm.VT);
  const uint32_t smP  = (uint32_t)__cvta_generic_to_shared(sm.Ps);

  const uint32_t qa_base = smQ + (uint32_t)((16 * wr + (lane & 15)) * QP * 4 + (lane >> 4) * 16);
  const uint32_t pa_base = smP + (uint32_t)((16 * wr + (lane & 15)) * PP * 4 + (lane >> 4) * 16);
  const uint32_t kb_base = smK + (uint32_t)((16 * wc + (lane & 7) + 8 * (lane >> 4)) * KP * 4 +
                                            ((lane >> 3) & 1) * 16);
  const uint32_t vb_base = smVT + (uint32_t)((32 * wc + (lane & 7) + 8 * (lane >> 4)) * VTP * 4 +
                                             ((lane >> 3) & 1) * 16);

  // ---- stage Q (tf32, once) ----
  {
    const float4* Qg = reinterpret_cast<const float4*>(Qb + (size_t)q0 * kD);
#pragma unroll
    for (int j = 0; j < 4; ++j) {
      const int f = tid + j * NT;
      const int r = f >> 5;
      float4 v = Qg[f];
      float4 t = make_float4(tff(v.x), tff(v.y), tff(v.z), tff(v.w));
      *reinterpret_cast<float4*>(&sm.Qs[r * QP + lane * 4]) = t;
    }
  }
  if (tid < TQ) sm.Zs[tid] = (float)q0;

  // ---- prefetch first K/V tile ----
  float4 kreg[4];
  float vreg[16];
  const int vd = 32 * (wid & 3) + lane;
  const int vt0 = 4 * (wid >> 2);
  {
    const float4* Kg = reinterpret_cast<const float4*>(Kb + (size_t)qt * TK * kD);
#pragma unroll
    for (int j = 0; j < 4; ++j) kreg[j] = Kg[tid + j * NT];
    const float* Vg = Vb + (size_t)qt * TK * kD;
#pragma unroll
    for (int j = 0; j < 4; ++j)
#pragma unroll
      for (int t = 0; t < 4; ++t)
        vreg[4 * j + t] = Vg[(size_t)(vt0 + 16 * j + t) * kD + vd];
  }

  float oacc[4][4];
#pragma unroll
  for (int j = 0; j < 4; ++j)
#pragma unroll
    for (int v = 0; v < 4; ++v) oacc[j][v] = 0.f;

  // ================= Phase 1: upper (incl diagonal) tiles =================
  for (int kt = qt; kt < NKT; ++kt) {
    const int k0 = kt * TK;
    __syncthreads();

    // ---- stage K (tf32) ----
#pragma unroll
    for (int j = 0; j < 4; ++j) {
      const int f = tid + j * NT;
      const int r = f >> 5;
      float4 t = make_float4(tff(kreg[j].x), tff(kreg[j].y),
                             tff(kreg[j].z), tff(kreg[j].w));
      *reinterpret_cast<float4*>(&sm.Ks[r * KP + lane * 4]) = t;
    }
    // ---- stage V transposed (tf32): VT[d][tok], conflict-free pitch ----
#pragma unroll
    for (int j = 0; j < 4; ++j) {
      float4 t = make_float4(tff(vreg[4 * j + 0]), tff(vreg[4 * j + 1]),
                             tff(vreg[4 * j + 2]), tff(vreg[4 * j + 3]));
      *reinterpret_cast<float4*>(&sm.VT[vd * VTP + vt0 + 16 * j]) = t;
    }
    // prefetch next tile
    if (kt + 1 < NKT) {
      const float4* Kg = reinterpret_cast<const float4*>(Kb + (size_t)(k0 + TK) * kD);
#pragma unroll
      for (int j = 0; j < 4; ++j) kreg[j] = Kg[tid + j * NT];
      const float* Vg = Vb + (size_t)(k0 + TK) * kD;
#pragma unroll
      for (int j = 0; j < 4; ++j)
#pragma unroll
        for (int t = 0; t < 4; ++t)
          vreg[4 * j + t] = Vg[(size_t)(vt0 + 16 * j + t) * kD + vd];
    }
    __syncthreads();

    // ---- QK^T ----
    float sacc[2][4];
#pragma unroll
    for (int j = 0; j < 2; ++j)
#pragma unroll
      for (int v = 0; v < 4; ++v) sacc[j][v] = 0.f;
#pragma unroll
    for (int s = 0; s < 16; ++s) {
      uint32_t a0, a1, a2, a3, b0, b1, b2, b3;
      ldm_x4(a0, a1, a2, a3, qa_base + (uint32_t)(s * 32));
      ldm_x4(b0, b1, b2, b3, kb_base + (uint32_t)(s * 32));
      mma_tf32(sacc[0], a0, a1, a2, a3, b0, b1);
      mma_tf32(sacc[1], a0, a1, a2, a3, b2, b3);
    }

    // ---- mask + exp (hybrid); attn store; Ps store; Z partials ----
    const bool diag = (kt == qt);
    float rs0 = 0.f, rs1 = 0.f;
    float* arow0 = attnb + (size_t)(q0 + r0) * kS + k0;
    float* arow1 = attnb + (size_t)(q0 + r1) * kS + k0;
#pragma unroll
    for (int j = 0; j < 2; ++j) {
      const int c = 16 * wc + 8 * j + 2 * tig;
      float x00 = exp_mufu(sacc[j][0]);
      float x01 = exp_mufu(sacc[j][1]);
      float x10 = (j == 1) ? exp_poly(sacc[j][2]) : exp_mufu(sacc[j][2]);
      float x11 = (j == 1) ? exp_poly(sacc[j][3]) : exp_mufu(sacc[j][3]);
      float e00, e01, e10, e11;
      if (diag) {
        e00 = (c     > r0) ? x00 : 1.0f;
        e01 = (c + 1 > r0) ? x01 : 1.0f;
        e10 = (c     > r1) ? x10 : 1.0f;
        e11 = (c + 1 > r1) ? x11 : 1.0f;
      } else {
        e00 = x00; e01 = x01; e10 = x10; e11 = x11;
      }
      rs0 += e00 + e01;
      rs1 += e10 + e11;
      *reinterpret_cast<float2*>(arow0 + c) = make_float2(e00, e01);
      *reinterpret_cast<float2*>(arow1 + c) = make_float2(e10, e11);
      *reinterpret_cast<float2*>(&sm.Ps[r0 * PP + c]) = make_float2(tff(e00), tff(e01));
      *reinterpret_cast<float2*>(&sm.Ps[r1 * PP + c]) = make_float2(tff(e10), tff(e11));
    }
    rs0 += __shfl_xor_sync(0xffffffffu, rs0, 1, 4);
    rs0 += __shfl_xor_sync(0xffffffffu, rs0, 2, 4);
    rs1 += __shfl_xor_sync(0xffffffffu, rs1, 1, 4);
    rs1 += __shfl_xor_sync(0xffffffffu, rs1, 2, 4);
    if (tig == 0) { sm.Zp[wc][r0] = rs0; sm.Zp[wc][r1] = rs1; }
    __syncthreads();
    if (tid < TQ)
      sm.Zs[tid] += (sm.Zp[0][tid] + sm.Zp[1][tid]) +
                    (sm.Zp[2][tid] + sm.Zp[3][tid]);

    // ---- PV ----
#pragma unroll
    for (int kk = 0; kk < 8; ++kk) {
      uint32_t a0, a1, a2, a3;
      ldm_x4(a0, a1, a2, a3, pa_base + (uint32_t)(kk * 32));
#pragma unroll
      for (int t = 0; t < 2; ++t) {
        uint32_t b0, b1, b2, b3;
        ldm_x4(b0, b1, b2, b3,
               vb_base + (uint32_t)(t * 16 * VTP * 4 + kk * 32));
        mma_tf32(oacc[2 * t + 0], a0, a1, a2, a3, b0, b1);
        mma_tf32(oacc[2 * t + 1], a0, a1, a2, a3, b2, b3);
      }
    }
  }

  // ================= Phase 2 =================
  __syncthreads();
  if (tid < TQ) sm.rZs[tid] = 1.0f / sm.Zs[tid];
  __syncthreads();

  // lower-region V column sums
  {
    const int vc = tid & 127, vq = tid >> 7;
    float a0 = 0.f, a1 = 0.f, a2 = 0.f, a3 = 0.f;
    for (int t = vq; t < q0; t += 16) {
      a0 += Vb[(size_t)t * kD + vc];
      a1 += Vb[(size_t)(t + 4) * kD + vc];
      a2 += Vb[(size_t)(t + 8) * kD + vc];
      a3 += Vb[(size_t)(t + 12) * kD + vc];
    }
    sm.Vps[vq][vc] = (a0 + a1) + (a2 + a3);
  }

  // lower attn fill = 1/Z
  const int ftr = tid >> 4, ftc = tid & 15;
  for (int kt = 0; kt < qt; ++kt) {
    const int k0 = kt * TK;
#pragma unroll
    for (int p = 0; p < 2; ++p) {
      const int r = ftr + 32 * p;
      const float rz = sm.rZs[r];
      *reinterpret_cast<float4*>(&attnb[(size_t)(q0 + r) * kS + k0 + 4 * ftc]) =
          make_float4(rz, rz, rz, rz);
    }
  }
  __syncthreads();
  if (tid < kD)
    sm.Vcsum[tid] = (sm.Vps[0][tid] + sm.Vps[1][tid]) +
                    (sm.Vps[2][tid] + sm.Vps[3][tid]);
  __syncthreads();

  // rescale upper attn tiles (2 k-tiles in flight)
  {
    const float rzA = sm.rZs[ftr];
    const float rzB = sm.rZs[ftr + 32];
    int kt = qt;
    for (; kt + 1 < NKT; kt += 2) {
      float4* p00 = reinterpret_cast<float4*>(&attnb[(size_t)(q0 + ftr) * kS + kt * TK + 4 * ftc]);
      float4* p01 = reinterpret_cast<float4*>(&attnb[(size_t)(q0 + ftr + 32) * kS + kt * TK + 4 * ftc]);
      float4* p10 = reinterpret_cast<float4*>(&attnb[(size_t)(q0 + ftr) * kS + (kt + 1) * TK + 4 * ftc]);
      float4* p11 = reinterpret_cast<float4*>(&attnb[(size_t)(q0 + ftr + 32) * kS + (kt + 1) * TK + 4 * ftc]);
      float4 v00 = *p00, v01 = *p01, v10 = *p10, v11 = *p11;
      v00.x *= rzA; v00.y *= rzA; v00.z *= rzA; v00.w *= rzA;
      v01.x *= rzB; v01.y *= rzB; v01.z *= rzB; v01.w *= rzB;
      v10.x *= rzA; v10.y *= rzA; v10.z *= rzA; v10.w *= rzA;
      v11.x *= rzB; v11.y *= rzB; v11.z *= rzB; v11.w *= rzB;
      *p00 = v00; *p01 = v01; *p10 = v10; *p11 = v11;
    }
    if (kt < NKT) {
      float4* p00 = reinterpret_cast<float4*>(&attnb[(size_t)(q0 + ftr) * kS + kt * TK + 4 * ftc]);
      float4* p01 = reinterpret_cast<float4*>(&attnb[(size_t)(q0 + ftr + 32) * kS + kt * TK + 4 * ftc]);
      float4 v00 = *p00, v01 = *p01;
      v00.x *= rzA; v00.y *= rzA; v00.z *= rzA; v00.w *= rzA;
      v01.x *= rzB; v01.y *= rzB; v01.z *= rzB; v01.w *= rzB;
      *p00 = v00; *p01 = v01;
    }
  }

  // final output
  {
    const float rz0 = sm.rZs[r0], rz1 = sm.rZs[r1];
#pragma unroll
    for (int j = 0; j < 4; ++j) {
      const int c = 32 * wc + 8 * j + 2 * tig;
      const float vs0 = sm.Vcsum[c], vs1 = sm.Vcsum[c + 1];
      float2 o0 = make_float2(rz0 * (oacc[j][0] + vs0), rz0 * (oacc[j][1] + vs1));
      float2 o1 = make_float2(rz1 * (oacc[j][2] + vs0), rz1 * (oacc[j][3] + vs1));
      *reinterpret_cast<float2*>(&outb[(size_t)(q0 + r0) * kD + c]) = o0;
      *reinterpret_cast<float2*>(&outb[(size_t)(q0 + r1) * kD + c]) = o1;
    }
  }
}

extern "C" void kernel_launch(void* const* d_in, const int* in_sizes, int n_in,
                              void* d_out, int out_size) {
  (void)in_sizes; (void)n_in; (void)out_size;
  const float* Q = (const float*)d_in[0];
  const float* K = (const float*)d_in[1];
  const float* V = (const float*)d_in[2];
  float* out  = (float*)d_out;
  float* attn = out + (size_t)kB * kS * kD;

  cudaFuncSetAttribute(sdpa_kernel, cudaFuncAttributeMaxDynamicSharedMemorySize,
                       SMEM_BYTES);
  dim3 grid(NKT, kB);
  sdpa_kernel<<<grid, NT, SMEM_BYTES>>>(Q, K, V, out, attn);
}